// round 15
// baseline (speedup 1.0000x reference)
#include <cuda_runtime.h>
#include <cuda_fp16.h>
#include <math.h>
#include <stdint.h>

// Problem constants
#define B_  4
#define S_  1024
#define D_  1024
#define H_  16
#define DKH_ 32
#define DV_  64

// ---------------------------------------------------------------------------
// Scratch (device globals; no allocations allowed) — all fp16 hi-only
// ---------------------------------------------------------------------------
__device__ __half pQh[4096*512];
__device__ __half pKh[4096*512];
__device__ __half pVh_[4096*1024];
__device__ __half pWh[6*512*512];
__device__ __half g_Q1h[64*1024*32];   // pre-scaled by log2e/sqrt(32)
__device__ __half g_K1h[64*1024*32];
__device__ __half g_Vh [64*1024*64];
__device__ __half qkvh[4096*1024];
__device__ float g_tmp[B_*S_*D_];

// ===========================================================================
// helpers
// ===========================================================================
__device__ __forceinline__ uint32_t smem_u32(const void* p) {
    uint32_t a;
    asm("{ .reg .u64 t; cvta.to.shared.u64 t, %1; cvt.u32.u64 %0, t; }"
        : "=r"(a) : "l"(p));
    return a;
}
__device__ __forceinline__ void ldsm_x4(uint32_t& r0, uint32_t& r1,
                                        uint32_t& r2, uint32_t& r3, uint32_t addr) {
    asm volatile("ldmatrix.sync.aligned.m8n8.x4.shared.b16 {%0,%1,%2,%3}, [%4];"
                 : "=r"(r0), "=r"(r1), "=r"(r2), "=r"(r3) : "r"(addr));
}
__device__ __forceinline__ void ldsm_x4t(uint32_t& r0, uint32_t& r1,
                                         uint32_t& r2, uint32_t& r3, uint32_t addr) {
    asm volatile("ldmatrix.sync.aligned.m8n8.x4.trans.shared.b16 {%0,%1,%2,%3}, [%4];"
                 : "=r"(r0), "=r"(r1), "=r"(r2), "=r"(r3) : "r"(addr));
}
__device__ __forceinline__ void ldsm_x2t(uint32_t& r0, uint32_t& r1, uint32_t addr) {
    asm volatile("ldmatrix.sync.aligned.m8n8.x2.trans.shared.b16 {%0,%1}, [%2];"
                 : "=r"(r0), "=r"(r1) : "r"(addr));
}
__device__ __forceinline__ void mma_f16(float* c, uint32_t a0, uint32_t a1,
                                        uint32_t a2, uint32_t a3,
                                        uint32_t b0, uint32_t b1) {
    asm volatile("mma.sync.aligned.m16n8k16.row.col.f32.f16.f16.f32 "
                 "{%0,%1,%2,%3}, {%4,%5,%6,%7}, {%8,%9}, {%0,%1,%2,%3};"
                 : "+f"(c[0]), "+f"(c[1]), "+f"(c[2]), "+f"(c[3])
                 : "r"(a0), "r"(a1), "r"(a2), "r"(a3), "r"(b0), "r"(b1));
}
__device__ __forceinline__ float ex2f(float x) {
    float r;
    asm("ex2.approx.f32 %0, %1;" : "=f"(r) : "f"(x));
    return r;
}
__device__ __forceinline__ uint32_t ex2_h2(uint32_t x) {
    uint32_t r;
    asm("ex2.approx.f16x2 %0, %1;" : "=r"(r) : "r"(x));
    return r;
}
__device__ __forceinline__ uint32_t pack_h2(float x, float y) {
    __half2 t = __floats2half2_rn(x, y);
    return *reinterpret_cast<uint32_t*>(&t);
}
__device__ __forceinline__ float2 h2_to_f2(uint32_t h) {
    __half2 t = *reinterpret_cast<__half2*>(&h);
    return __half22float2(t);
}
__device__ __forceinline__ void cp16(uint32_t dst, const void* src) {
    asm volatile("cp.async.cg.shared.global [%0], [%1], 16;"
                 :: "r"(dst), "l"(src));
}
#define CP_COMMIT()  asm volatile("cp.async.commit_group;" ::: "memory")
#define CP_WAIT(N)   asm volatile("cp.async.wait_group %0;" :: "n"(N) : "memory")

// ===========================================================================
// presplit: fp32 -> fp16 hi for all GEMM operands. (unchanged)
// ===========================================================================
__global__ void __launch_bounds__(256)
presplit(const float* __restrict__ inQ, const float* __restrict__ inK,
         const float* __restrict__ inV,
         const float* __restrict__ W0, const float* __restrict__ W1,
         const float* __restrict__ W2, const float* __restrict__ W3,
         const float* __restrict__ W4, const float* __restrict__ W5)
{
    const int seg = blockIdx.y;
    const int gid = blockIdx.x * 256 + threadIdx.x;
    const int stride4 = gridDim.x * 256 * 4;

    if (seg < 2) {
        const float* s = seg ? inK : inQ;
        __half* dh = seg ? pKh : pQh;
        for (int i = gid * 4; i < 4096 * 512; i += stride4) {
            int row = i >> 9, col = i & 511;
            float4 v = *(const float4*)&s[(size_t)row * 1024 + col];
            *(uint2*)&dh[i] = make_uint2(pack_h2(v.x, v.y), pack_h2(v.z, v.w));
        }
    } else if (seg == 2) {
        for (int i = gid * 4; i < 4096 * 1024; i += stride4) {
            float4 v = *(const float4*)&inV[i];
            *(uint2*)&pVh_[i] = make_uint2(pack_h2(v.x, v.y), pack_h2(v.z, v.w));
        }
    } else {
        const int w = seg - 3;
        const float* s = (w == 0) ? W0 : (w == 1) ? W1 : (w == 2) ? W2
                       : (w == 3) ? W3 : (w == 4) ? W4 : W5;
        __half* dh = pWh + (size_t)w * 262144;
        for (int i = gid * 4; i < 262144; i += stride4) {
            float4 v = *(const float4*)&s[i];
            *(uint2*)&dh[i] = make_uint2(pack_h2(v.x, v.y), pack_h2(v.z, v.w));
        }
    }
}

// ===========================================================================
// HMMA GEMM, 1-term fp16: 512 threads / 16 warps, CTA tile 256x128,
// warp tile 64x32, K chunk 64, 2-stage cp.async pipeline (8 syncs/CTA).
// mode: 0=Q1(scaled), 1=K1, 2=V1, 3=V2, 4=FC half0 (+res), 5=FC half1 (+res)
// ===========================================================================
#define GAP 144      /* A smem row pitch: 64 fp16 = 128B + 16 pad */
#define GBP 272      /* B smem row pitch: 128 fp16 = 256B + 16 pad */
#define GST_SZ  54272u
#define GST_A(s) ((s) * GST_SZ)
#define GST_B(s) ((s) * GST_SZ + 36864u)
#define GEMM_SMEM (2 * 54272)

__global__ void __launch_bounds__(512, 1)
mma_gemm(const float* __restrict__ inQ, int mode_base)
{
    extern __shared__ unsigned char sm[];
    const uint32_t smb = smem_u32(sm);

    const int mode = mode_base + blockIdx.z;
    const __half *pAh;
    int apitch, aoff;
    switch (mode) {
        case 0: pAh = pQh;  apitch = 512;  aoff = 0;   break;
        case 1: pAh = pKh;  apitch = 512;  aoff = 0;   break;
        case 2: pAh = pVh_; apitch = 1024; aoff = 0;   break;
        case 3: pAh = pVh_; apitch = 1024; aoff = 512; break;
        case 4: pAh = qkvh; apitch = 1024; aoff = 0;   break;
        default:pAh = qkvh; apitch = 1024; aoff = 512; break;
    }
    const __half* wh = pWh + (size_t)mode * 262144;

    const int m0 = blockIdx.x * 256;
    const int n0 = blockIdx.y * 128;
    const int tid  = threadIdx.x;
    const int wid  = tid >> 5;
    const int lane = tid & 31;
    const int wy = wid >> 2;        // 0..3 (64 rows each)
    const int wx = wid & 3;         // 0..3 (32 cols each)

    // fills per chunk: A 256x64 fp16 = 2048 cp16 (4/thread); B 64x128 = 1024 (2/thread)
    const int ar = tid >> 1, a4 = (tid & 1) * 4;   // 2 thr/row, 4 segs each
    const int br = tid >> 3, b2 = (tid & 7) * 2;   // 8 thr/row, 2 segs each

    #define GFILL(st, k0)                                                         \
    {                                                                             \
        const __half* sha = pAh + (size_t)(m0 + ar) * apitch + aoff + (k0) + a4 * 8; \
        uint32_t da = (uint32_t)(ar * GAP + a4 * 16);                             \
        _Pragma("unroll")                                                         \
        for (int u_ = 0; u_ < 4; ++u_)                                            \
            cp16(smb + GST_A(st) + da + u_ * 16, sha + u_ * 8);                   \
        const __half* shb = wh + (size_t)((k0) + br) * 512 + n0 + b2 * 8;         \
        uint32_t db = (uint32_t)(br * GBP + b2 * 16);                             \
        cp16(smb + GST_B(st) + db,      shb);                                     \
        cp16(smb + GST_B(st) + db + 16, shb + 8);                                 \
        CP_COMMIT();                                                              \
    }

    float c[4][4][4] = {};

    const int a_row_in_tile = lane & 15;
    const int a_kseg        = (lane >> 4) & 1;
    const int b_krow        = (lane & 7) + ((lane >> 3) & 1) * 8;

    GFILL(0, 0);

    for (int chunk = 0; chunk < 8; ++chunk) {
        CP_WAIT(0);
        __syncthreads();
        if (chunk + 1 < 8) GFILL((chunk + 1) & 1, (chunk + 1) * 64);

        const int cs = chunk & 1;
        const uint32_t ahb = smb + GST_A(cs);
        const uint32_t bhb = smb + GST_B(cs);

        #pragma unroll
        for (int ks = 0; ks < 4; ++ks) {
            uint32_t ahf[4][4];
            #pragma unroll
            for (int mt = 0; mt < 4; ++mt) {
                int row = wy * 64 + mt * 16 + a_row_in_tile;
                uint32_t aoffb = (uint32_t)(row * GAP + ks * 32 + a_kseg * 16);
                ldsm_x4(ahf[mt][0], ahf[mt][1], ahf[mt][2], ahf[mt][3], ahb + aoffb);
            }
            uint32_t bhf[4][2];
            #pragma unroll
            for (int nt = 0; nt < 4; ++nt) {
                uint32_t boffb = (uint32_t)((ks * 16 + b_krow) * GBP
                                            + (wx * 32 + nt * 8) * 2);
                ldsm_x2t(bhf[nt][0], bhf[nt][1], bhb + boffb);
            }
            #pragma unroll
            for (int mt = 0; mt < 4; ++mt) {
                #pragma unroll
                for (int nt = 0; nt < 4; ++nt) {
                    mma_f16(c[mt][nt], ahf[mt][0], ahf[mt][1], ahf[mt][2], ahf[mt][3],
                            bhf[nt][0], bhf[nt][1]);
                }
            }
        }
    }

    // ---- epilogue ----
    const int gid = lane >> 2;
    const int tig = lane & 3;

    #pragma unroll
    for (int mt = 0; mt < 4; ++mt) {
        int row = m0 + wy * 64 + mt * 16 + gid;
        int b = row >> 10, s = row & 1023;
        #pragma unroll
        for (int nt = 0; nt < 4; ++nt) {
            int col = n0 + wx * 32 + nt * 8 + tig * 2;
            float2 v01 = make_float2(c[mt][nt][0], c[mt][nt][1]);
            float2 v23 = make_float2(c[mt][nt][2], c[mt][nt][3]);
            if (mode <= 1) {
                int h = col >> 5, d = col & 31;
                __half* dh = (mode == 0) ? g_Q1h : g_K1h;
                // Q scale: log2(e)/sqrt(32) so softmax uses ex2 directly
                float sc = (mode == 0) ? 0.25503487350122697f : 1.0f;
                size_t base = ((size_t)(b * 16 + h) * 1024) * 32 + d;
                *(uint32_t*)&dh[base + (size_t)s * 32]       = pack_h2(v01.x * sc, v01.y * sc);
                *(uint32_t*)&dh[base + (size_t)(s + 8) * 32] = pack_h2(v23.x * sc, v23.y * sc);
            } else if (mode <= 3) {
                int h = col >> 5, d = (col & 31) + (mode == 3 ? 32 : 0);
                size_t base = ((size_t)(b * 16 + h) * 1024) * 64 + d;
                *(uint32_t*)&g_Vh[base + (size_t)s * 64]       = pack_h2(v01.x, v01.y);
                *(uint32_t*)&g_Vh[base + (size_t)(s + 8) * 64] = pack_h2(v23.x, v23.y);
            } else {
                int half = mode - 4;
                size_t idx0 = (size_t)row * 1024 + half * 512 + col;
                size_t idx1 = idx0 + 8 * 1024;
                float2 r0 = *(const float2*)&inQ[idx0];
                float2 r1 = *(const float2*)&inQ[idx1];
                *(float2*)&g_tmp[idx0] = make_float2(v01.x + r0.x, v01.y + r0.y);
                *(float2*)&g_tmp[idx1] = make_float2(v23.x + r1.x, v23.y + r1.y);
            }
        }
    }
    #undef GFILL
}

// ===========================================================================
// Flash attention: 1 slab/CTA, 1024 CTAs, LPT, fp16 1-term, 5 CTAs/SM.
// Pass-1 exp via ex2.approx.f16x2 (half the MUFU ops); pass-2 fp32 ex2.
// ===========================================================================
#define AT_K_H(buf) ((buf) * 5120u)
#define AT_V_H(buf) (10240u + (buf) * 9216u)
#define AT_Q_H 10240u
#define ATTN_SMEM 28672

__global__ void __launch_bounds__(128, 5)
attn_flash(float* __restrict__ Pout)
{
    extern __shared__ unsigned char sm[];
    const uint32_t smb = smem_u32(sm);

    const int bh = blockIdx.x;
    const int qs = 15 - (int)blockIdx.y;
    const int q0 = qs * 64;
    const int nkt = qs + 1;
    const int ncol = nkt * 64;
    const int tid = threadIdx.x, wid = tid >> 5, lane = tid & 31;

    const int frow = tid >> 1;
    const int fs2  = (tid & 1) * 2;
    const int fs4  = (tid & 1) * 4;

#define KFILL(buf, kt)                                                            \
    {                                                                             \
        const __half* sh_ = g_K1h + ((size_t)bh*1024 + (size_t)(kt)*64 + frow)*32 + fs2*8; \
        uint32_t d_ = (uint32_t)(frow * 80 + fs2 * 16);                           \
        cp16(smb + AT_K_H(buf) + d_,      sh_);                                   \
        cp16(smb + AT_K_H(buf) + d_ + 16, sh_ + 8);                               \
    }
#define VFILL(buf, kt)                                                            \
    {                                                                             \
        const __half* sh_ = g_Vh + ((size_t)bh*1024 + (size_t)(kt)*64 + frow)*64 + fs4*8; \
        uint32_t d_ = (uint32_t)(frow * 144 + fs4 * 16);                          \
        _Pragma("unroll")                                                         \
        for (int u_ = 0; u_ < 4; ++u_)                                            \
            cp16(smb + AT_V_H(buf) + d_ + u_*16, sh_ + u_*8);                     \
    }

    KFILL(0, 0); CP_COMMIT();

    {
        const __half* qh = g_Q1h + ((size_t)bh*1024 + q0 + frow)*32 + fs2*8;
        uint32_t d = (uint32_t)(frow * 80 + fs2 * 16);
        *(uint4*)(sm + AT_Q_H + d)      = *(const uint4*)qh;
        *(uint4*)(sm + AT_Q_H + d + 16) = *(const uint4*)(qh + 8);
    }
    __syncthreads();

    uint32_t qfh[2][4];
    #pragma unroll
    for (int ks = 0; ks < 2; ++ks) {
        uint32_t off = (uint32_t)((wid * 16 + (lane & 15)) * 80
                                  + ks * 32 + ((lane >> 4) & 1) * 16);
        ldsm_x4(qfh[ks][0], qfh[ks][1], qfh[ks][2], qfh[ks][3], smb + AT_Q_H + off);
    }

    const int gr0 = q0 + wid * 16 + (lane >> 2);
    const uint32_t kfoff = (uint32_t)(((lane & 7)) * 80 + (lane >> 3) * 16);

    #define SCOMP(buf)                                                            \
    {                                                                             \
        const uint32_t khb = smb + AT_K_H(buf) + kfoff;                           \
        _Pragma("unroll")                                                         \
        for (int nt = 0; nt < 8; ++nt) {                                          \
            uint32_t kb[4];                                                       \
            ldsm_x4(kb[0], kb[1], kb[2], kb[3], khb + (uint32_t)(nt * 8 * 80));   \
            mma_f16(s[nt], qfh[0][0], qfh[0][1], qfh[0][2], qfh[0][3], kb[0], kb[1]); \
            mma_f16(s[nt], qfh[1][0], qfh[1][1], qfh[1][2], qfh[1][3], kb[2], kb[3]); \
        }                                                                         \
    }
    #define SMASK(kt)                                                             \
    if ((kt) == nkt - 1) {                                                        \
        int cb = (kt) * 64 + (lane & 3) * 2;                                      \
        _Pragma("unroll")                                                         \
        for (int nt = 0; nt < 8; ++nt) {                                          \
            int c0 = cb + nt * 8;                                                 \
            if (c0     > gr0)     s[nt][0] = -1e30f;                              \
            if (c0 + 1 > gr0)     s[nt][1] = -1e30f;                              \
            if (c0     > gr0 + 8) s[nt][2] = -1e30f;                              \
            if (c0 + 1 > gr0 + 8) s[nt][3] = -1e30f;                              \
        }                                                                         \
    }

    // ================= Pass 1: l = sum exp2(s), f16x2 MUFU =================
    float l0 = 0.f, l1 = 0.f;

    for (int kt = 0; kt < nkt; ++kt) {
        CP_WAIT(0);
        __syncthreads();
        if (kt + 1 < nkt) { KFILL((kt + 1) & 1, kt + 1); CP_COMMIT(); }

        float s[8][4] = {};
        SCOMP(kt & 1);
        SMASK(kt);

        float a0 = 0.f, a1 = 0.f;
        #pragma unroll
        for (int nt = 0; nt < 8; ++nt) {
            // fp16x2 exp: masked -1e30 packs to -inf -> ex2 -> exactly 0
            float2 e01 = h2_to_f2(ex2_h2(pack_h2(s[nt][0], s[nt][1])));
            float2 e23 = h2_to_f2(ex2_h2(pack_h2(s[nt][2], s[nt][3])));
            a0 += e01.x + e01.y;
            a1 += e23.x + e23.y;
        }
        a0 += __shfl_xor_sync(0xffffffffu, a0, 1);
        a0 += __shfl_xor_sync(0xffffffffu, a0, 2);
        a1 += __shfl_xor_sync(0xffffffffu, a1, 1);
        a1 += __shfl_xor_sync(0xffffffffu, a1, 2);
        l0 += a0;
        l1 += a1;
    }
    const float li0 = 1.0f / l0, li1 = 1.0f / l1;

    // ================= Pass 2: P write + O = P @ V =================
    __syncthreads();
    KFILL(0, 0); VFILL(0, 0); CP_COMMIT();

    float o[8][4] = {};

    for (int kt = 0; kt < nkt; ++kt) {
        CP_WAIT(0);
        __syncthreads();
        if (kt + 1 < nkt) {
            KFILL((kt + 1) & 1, kt + 1);
            VFILL((kt + 1) & 1, kt + 1);
            CP_COMMIT();
        }

        float s[8][4] = {};
        SCOMP(kt & 1);
        SMASK(kt);

        #pragma unroll
        for (int nt = 0; nt < 8; ++nt) {
            s[nt][0] = ex2f(s[nt][0]) * li0;
            s[nt][1] = ex2f(s[nt][1]) * li0;
            s[nt][2] = ex2f(s[nt][2]) * li1;
            s[nt][3] = ex2f(s[nt][3]) * li1;
        }

        {
            float* pr0 = Pout + ((size_t)bh * 1024 + gr0) * 1024 + kt * 64 + (lane & 3) * 2;
            float* pr1 = pr0 + 8 * 1024;
            #pragma unroll
            for (int nt = 0; nt < 8; ++nt) {
                *(float2*)&pr0[nt * 8] = make_float2(s[nt][0], s[nt][1]);
                *(float2*)&pr1[nt * 8] = make_float2(s[nt][2], s[nt][3]);
            }
        }

        const uint32_t vhb = smb + AT_V_H(kt & 1);
        #pragma unroll
        for (int ksv = 0; ksv < 4; ++ksv) {
            uint32_t ah[4];
            ah[0] = pack_h2(s[2*ksv][0],   s[2*ksv][1]);
            ah[1] = pack_h2(s[2*ksv][2],   s[2*ksv][3]);
            ah[2] = pack_h2(s[2*ksv+1][0], s[2*ksv+1][1]);
            ah[3] = pack_h2(s[2*ksv+1][2], s[2*ksv+1][3]);
            uint32_t vrow = (uint32_t)((ksv * 16 + (lane & 7) + ((lane >> 3) & 1) * 8) * 144
                                       + (lane >> 4) * 16);
            #pragma unroll
            for (int ntv = 0; ntv < 8; ntv += 2) {
                uint32_t v0, v1, v2, v3;
                ldsm_x4t(v0, v1, v2, v3, vhb + vrow + ntv * 16);
                mma_f16(o[ntv],     ah[0], ah[1], ah[2], ah[3], v0, v1);
                mma_f16(o[ntv + 1], ah[0], ah[1], ah[2], ah[3], v2, v3);
            }
        }
    }

    // zero-fill P tail
    {
        float4 z = make_float4(0.f, 0.f, 0.f, 0.f);
        float* base0 = Pout + ((size_t)bh * 1024 + gr0) * 1024;
        float* base1 = base0 + 8 * 1024;
        for (int col = ncol + (lane & 3) * 4; col < 1024; col += 16) {
            *(float4*)&base0[col] = z;
            *(float4*)&base1[col] = z;
        }
    }

    // O epilogue -> qkvh (fp16)
    {
        const int b = bh >> 4, h = bh & 15;
        size_t i0 = ((size_t)(b * 1024 + gr0)) * 1024 + h * 64 + (lane & 3) * 2;
        size_t i1 = i0 + 8 * 1024;
        #pragma unroll
        for (int ntv = 0; ntv < 8; ++ntv) {
            *(uint32_t*)&qkvh[i0 + ntv * 8] = pack_h2(o[ntv][0], o[ntv][1]);
            *(uint32_t*)&qkvh[i1 + ntv * 8] = pack_h2(o[ntv][2], o[ntv][3]);
        }
    }
    #undef KFILL
    #undef VFILL
    #undef SCOMP
    #undef SMASK
}

// ---------------------------------------------------------------------------
// LayerNorm (unchanged)
// ---------------------------------------------------------------------------
__global__ void __launch_bounds__(256)
ln_kernel(const float* __restrict__ gamma,
          const float* __restrict__ beta,
          float* __restrict__ out)
{
    const int row = blockIdx.x;
    const int tid = threadIdx.x;
    const int c4  = tid * 4;
    const int hf  = tid >> 7;
    const int wrp = tid >> 5;

    float4 v = *(const float4*)&g_tmp[(size_t)row * 1024 + c4];
    float s  = v.x + v.y + v.z + v.w;
    float sq = v.x*v.x + v.y*v.y + v.z*v.z + v.w*v.w;
    #pragma unroll
    for (int off = 16; off > 0; off >>= 1) {
        s  += __shfl_xor_sync(0xffffffffu, s,  off);
        sq += __shfl_xor_sync(0xffffffffu, sq, off);
    }
    __shared__ float ss[8], sqq[8];
    if ((tid & 31) == 0) { ss[wrp] = s; sqq[wrp] = sq; }
    __syncthreads();
    float tot = 0.f, totq = 0.f;
    #pragma unroll
    for (int w = 0; w < 4; ++w) { tot += ss[hf * 4 + w]; totq += sqq[hf * 4 + w]; }

    float mu  = tot * (1.0f / 512.0f);
    float var = totq * (1.0f / 512.0f) - mu * mu;
    float rstd = rsqrtf(var + 1e-5f);

    int gc = c4 & 511;
    float4 g = *(const float4*)&gamma[gc];
    float4 b = *(const float4*)&beta[gc];
    float4 r;
    r.x = (v.x - mu) * rstd * g.x + b.x;
    r.y = (v.y - mu) * rstd * g.y + b.y;
    r.z = (v.z - mu) * rstd * g.z + b.z;
    r.w = (v.w - mu) * rstd * g.w + b.w;
    *(float4*)&out[(size_t)row * 1024 + c4] = r;
}

// ---------------------------------------------------------------------------
extern "C" void kernel_launch(void* const* d_in, const int* in_sizes, int n_in,
                              void* d_out, int out_size)
{
    const float* inQ  = (const float*)d_in[0];
    const float* inK  = (const float*)d_in[1];
    const float* inV  = (const float*)d_in[2];
    const float* WQ1  = (const float*)d_in[4];
    const float* WK1  = (const float*)d_in[5];
    const float* WV1  = (const float*)d_in[6];
    const float* WV2  = (const float*)d_in[9];
    const float* Wfc1 = (const float*)d_in[10];
    const float* Wfc2 = (const float*)d_in[11];
    const float* ln_g = (const float*)d_in[12];
    const float* ln_b = (const float*)d_in[13];

    float* out  = (float*)d_out;
    float* Pout = out + (size_t)B_ * S_ * D_;

    cudaFuncSetAttribute(attn_flash, cudaFuncAttributeMaxDynamicSharedMemorySize,
                         ATTN_SMEM);
    cudaFuncSetAttribute(mma_gemm, cudaFuncAttributeMaxDynamicSharedMemorySize,
                         GEMM_SMEM);

    // 0) convert GEMM operands to fp16
    presplit<<<dim3(256, 9), 256>>>(inQ, inK, inV, WQ1, WK1, WV1, WV2, Wfc1, Wfc2);
    // 1) projections: Q1, K1, V1, V2 (256x128 tiles, K-chunk 64)
    mma_gemm<<<dim3(16, 4, 4), 512, GEMM_SMEM>>>(inQ, 0);
    // 2) flash attention
    attn_flash<<<dim3(64, 16), 128, ATTN_SMEM>>>(Pout);
    // 3) FC + residual (single wave)
    mma_gemm<<<dim3(16, 4, 2), 512, GEMM_SMEM>>>(inQ, 4);
    // 4) LayerNorm -> final output
    ln_kernel<<<dim3(B_ * S_), 256>>>(ln_g, ln_b, out);
}

// round 16
// speedup vs baseline: 1.0691x; 1.0691x over previous
#include <cuda_runtime.h>
#include <cuda_fp16.h>
#include <math.h>
#include <stdint.h>

// Problem constants
#define B_  4
#define S_  1024
#define D_  1024
#define H_  16
#define DKH_ 32
#define DV_  64

// ---------------------------------------------------------------------------
// Scratch (device globals; no allocations allowed) — all fp16 hi-only
// ---------------------------------------------------------------------------
__device__ __half pQh[4096*512];
__device__ __half pKh[4096*512];
__device__ __half pVh_[4096*1024];
__device__ __half pWh[6*512*512];
__device__ __half g_Q1h[64*1024*32];   // pre-scaled by log2e/sqrt(32)
__device__ __half g_K1h[64*1024*32];
__device__ __half g_Vh [64*1024*64];
__device__ __half qkvh[4096*1024];
__device__ float g_tmp[B_*S_*D_];

// ===========================================================================
// helpers
// ===========================================================================
__device__ __forceinline__ uint32_t smem_u32(const void* p) {
    uint32_t a;
    asm("{ .reg .u64 t; cvta.to.shared.u64 t, %1; cvt.u32.u64 %0, t; }"
        : "=r"(a) : "l"(p));
    return a;
}
__device__ __forceinline__ void ldsm_x4(uint32_t& r0, uint32_t& r1,
                                        uint32_t& r2, uint32_t& r3, uint32_t addr) {
    asm volatile("ldmatrix.sync.aligned.m8n8.x4.shared.b16 {%0,%1,%2,%3}, [%4];"
                 : "=r"(r0), "=r"(r1), "=r"(r2), "=r"(r3) : "r"(addr));
}
__device__ __forceinline__ void ldsm_x4t(uint32_t& r0, uint32_t& r1,
                                         uint32_t& r2, uint32_t& r3, uint32_t addr) {
    asm volatile("ldmatrix.sync.aligned.m8n8.x4.trans.shared.b16 {%0,%1,%2,%3}, [%4];"
                 : "=r"(r0), "=r"(r1), "=r"(r2), "=r"(r3) : "r"(addr));
}
__device__ __forceinline__ void mma_f16(float* c, uint32_t a0, uint32_t a1,
                                        uint32_t a2, uint32_t a3,
                                        uint32_t b0, uint32_t b1) {
    asm volatile("mma.sync.aligned.m16n8k16.row.col.f32.f16.f16.f32 "
                 "{%0,%1,%2,%3}, {%4,%5,%6,%7}, {%8,%9}, {%0,%1,%2,%3};"
                 : "+f"(c[0]), "+f"(c[1]), "+f"(c[2]), "+f"(c[3])
                 : "r"(a0), "r"(a1), "r"(a2), "r"(a3), "r"(b0), "r"(b1));
}
__device__ __forceinline__ float ex2f(float x) {
    float r;
    asm("ex2.approx.f32 %0, %1;" : "=f"(r) : "f"(x));
    return r;
}
__device__ __forceinline__ uint32_t pack_h2(float x, float y) {
    __half2 t = __floats2half2_rn(x, y);
    return *reinterpret_cast<uint32_t*>(&t);
}
__device__ __forceinline__ void cp16(uint32_t dst, const void* src) {
    asm volatile("cp.async.cg.shared.global [%0], [%1], 16;"
                 :: "r"(dst), "l"(src));
}
#define CP_COMMIT()  asm volatile("cp.async.commit_group;" ::: "memory")
#define CP_WAIT(N)   asm volatile("cp.async.wait_group %0;" :: "n"(N) : "memory")

// ===========================================================================
// presplit: fp32 -> fp16 hi for all GEMM operands. (unchanged)
// ===========================================================================
__global__ void __launch_bounds__(256)
presplit(const float* __restrict__ inQ, const float* __restrict__ inK,
         const float* __restrict__ inV,
         const float* __restrict__ W0, const float* __restrict__ W1,
         const float* __restrict__ W2, const float* __restrict__ W3,
         const float* __restrict__ W4, const float* __restrict__ W5)
{
    const int seg = blockIdx.y;
    const int gid = blockIdx.x * 256 + threadIdx.x;
    const int stride4 = gridDim.x * 256 * 4;

    if (seg < 2) {
        const float* s = seg ? inK : inQ;
        __half* dh = seg ? pKh : pQh;
        for (int i = gid * 4; i < 4096 * 512; i += stride4) {
            int row = i >> 9, col = i & 511;
            float4 v = *(const float4*)&s[(size_t)row * 1024 + col];
            *(uint2*)&dh[i] = make_uint2(pack_h2(v.x, v.y), pack_h2(v.z, v.w));
        }
    } else if (seg == 2) {
        for (int i = gid * 4; i < 4096 * 1024; i += stride4) {
            float4 v = *(const float4*)&inV[i];
            *(uint2*)&pVh_[i] = make_uint2(pack_h2(v.x, v.y), pack_h2(v.z, v.w));
        }
    } else {
        const int w = seg - 3;
        const float* s = (w == 0) ? W0 : (w == 1) ? W1 : (w == 2) ? W2
                       : (w == 3) ? W3 : (w == 4) ? W4 : W5;
        __half* dh = pWh + (size_t)w * 262144;
        for (int i = gid * 4; i < 262144; i += stride4) {
            float4 v = *(const float4*)&s[i];
            *(uint2*)&dh[i] = make_uint2(pack_h2(v.x, v.y), pack_h2(v.z, v.w));
        }
    }
}

// ===========================================================================
// HMMA GEMM (R14 config restored): 512 threads / 16 warps, CTA tile 256x128,
// warp tile 64x32, K chunk 32, 3-stage cp.async pipeline.
// B fragments via ldsm_x4t (2 per ks-step instead of 4 x2t).
// mode: 0=Q1(scaled), 1=K1, 2=V1, 3=V2, 4=FC half0 (+res), 5=FC half1 (+res)
// ===========================================================================
#define APITCH 80
#define BPITCH 272
#define ST_SZ  29184u
#define ST_AH(s) ((s) * ST_SZ)
#define ST_BH(s) ((s) * ST_SZ + 20480u)
#define GEMM_SMEM (3 * 29184)

__global__ void __launch_bounds__(512, 1)
mma_gemm(const float* __restrict__ inQ, int mode_base)
{
    extern __shared__ unsigned char sm[];
    const uint32_t smb = smem_u32(sm);

    const int mode = mode_base + blockIdx.z;
    const __half *pAh;
    int apitch, aoff;
    switch (mode) {
        case 0: pAh = pQh;  apitch = 512;  aoff = 0;   break;
        case 1: pAh = pKh;  apitch = 512;  aoff = 0;   break;
        case 2: pAh = pVh_; apitch = 1024; aoff = 0;   break;
        case 3: pAh = pVh_; apitch = 1024; aoff = 512; break;
        case 4: pAh = qkvh; apitch = 1024; aoff = 0;   break;
        default:pAh = qkvh; apitch = 1024; aoff = 512; break;
    }
    const __half* wh = pWh + (size_t)mode * 262144;

    const int m0 = blockIdx.x * 256;
    const int n0 = blockIdx.y * 128;
    const int tid  = threadIdx.x;
    const int wid  = tid >> 5;
    const int lane = tid & 31;
    const int wy = wid >> 2;        // 0..3 (64 rows each)
    const int wx = wid & 3;         // 0..3 (32 cols each)

    const int ar = tid >> 1, aseg2 = (tid & 1) * 2;
    const int br = tid >> 4, bseg = tid & 15;

    #define GFILL(st, k0)                                                         \
    {                                                                             \
        const __half* sha = pAh + (size_t)(m0 + ar) * apitch + aoff + (k0) + aseg2 * 8; \
        uint32_t da = (uint32_t)(ar * APITCH + aseg2 * 16);                       \
        cp16(smb + ST_AH(st) + da,      sha);                                     \
        cp16(smb + ST_AH(st) + da + 16, sha + 8);                                 \
        const __half* shb = wh + (size_t)((k0) + br) * 512 + n0 + bseg * 8;       \
        cp16(smb + ST_BH(st) + (uint32_t)(br * BPITCH + bseg * 16), shb);         \
        CP_COMMIT();                                                              \
    }

    float c[4][4][4] = {};

    const int a_row_in_tile = lane & 15;
    const int a_kseg        = (lane >> 4) & 1;
    const int b_krow        = (lane & 7) + ((lane >> 3) & 1) * 8;
    const int b_colsel     = (lane >> 4) * 16;    // x4t: hi-lanes take +8 cols

    GFILL(0, 0);
    GFILL(1, 32);

    for (int chunk = 0; chunk < 16; ++chunk) {
        if (chunk + 1 < 16) { CP_WAIT(1); } else { CP_WAIT(0); }
        __syncthreads();
        if (chunk + 2 < 16) {
            int st = (chunk + 2) % 3;
            GFILL(st, (chunk + 2) * 32);
        }
        const int cs = chunk % 3;
        const uint32_t ahb = smb + ST_AH(cs);
        const uint32_t bhb = smb + ST_BH(cs);

        #pragma unroll
        for (int ks = 0; ks < 2; ++ks) {
            uint32_t ahf[4][4];
            #pragma unroll
            for (int mt = 0; mt < 4; ++mt) {
                int row = wy * 64 + mt * 16 + a_row_in_tile;
                uint32_t aoffb = (uint32_t)(row * APITCH + ks * 32 + a_kseg * 16);
                ldsm_x4(ahf[mt][0], ahf[mt][1], ahf[mt][2], ahf[mt][3], ahb + aoffb);
            }
            uint32_t bhf[4][2];
            #pragma unroll
            for (int nt2 = 0; nt2 < 4; nt2 += 2) {
                uint32_t boffb = (uint32_t)((ks * 16 + b_krow) * BPITCH
                                            + (wx * 32 + nt2 * 8) * 2 + b_colsel);
                ldsm_x4t(bhf[nt2][0], bhf[nt2][1], bhf[nt2+1][0], bhf[nt2+1][1],
                         bhb + boffb);
            }
            #pragma unroll
            for (int mt = 0; mt < 4; ++mt) {
                #pragma unroll
                for (int nt = 0; nt < 4; ++nt) {
                    mma_f16(c[mt][nt], ahf[mt][0], ahf[mt][1], ahf[mt][2], ahf[mt][3],
                            bhf[nt][0], bhf[nt][1]);
                }
            }
        }
    }

    // ---- epilogue ----
    const int gid = lane >> 2;
    const int tig = lane & 3;

    #pragma unroll
    for (int mt = 0; mt < 4; ++mt) {
        int row = m0 + wy * 64 + mt * 16 + gid;
        int b = row >> 10, s = row & 1023;
        #pragma unroll
        for (int nt = 0; nt < 4; ++nt) {
            int col = n0 + wx * 32 + nt * 8 + tig * 2;
            float2 v01 = make_float2(c[mt][nt][0], c[mt][nt][1]);
            float2 v23 = make_float2(c[mt][nt][2], c[mt][nt][3]);
            if (mode <= 1) {
                int h = col >> 5, d = col & 31;
                __half* dh = (mode == 0) ? g_Q1h : g_K1h;
                // Q scale: log2(e)/sqrt(32) so softmax uses ex2 directly
                float sc = (mode == 0) ? 0.25503487350122697f : 1.0f;
                size_t base = ((size_t)(b * 16 + h) * 1024) * 32 + d;
                *(uint32_t*)&dh[base + (size_t)s * 32]       = pack_h2(v01.x * sc, v01.y * sc);
                *(uint32_t*)&dh[base + (size_t)(s + 8) * 32] = pack_h2(v23.x * sc, v23.y * sc);
            } else if (mode <= 3) {
                int h = col >> 5, d = (col & 31) + (mode == 3 ? 32 : 0);
                size_t base = ((size_t)(b * 16 + h) * 1024) * 64 + d;
                *(uint32_t*)&g_Vh[base + (size_t)s * 64]       = pack_h2(v01.x, v01.y);
                *(uint32_t*)&g_Vh[base + (size_t)(s + 8) * 64] = pack_h2(v23.x, v23.y);
            } else {
                int half = mode - 4;
                size_t idx0 = (size_t)row * 1024 + half * 512 + col;
                size_t idx1 = idx0 + 8 * 1024;
                float2 r0 = *(const float2*)&inQ[idx0];
                float2 r1 = *(const float2*)&inQ[idx1];
                *(float2*)&g_tmp[idx0] = make_float2(v01.x + r0.x, v01.y + r0.y);
                *(float2*)&g_tmp[idx1] = make_float2(v23.x + r1.x, v23.y + r1.y);
            }
        }
    }
    #undef GFILL
}

// ===========================================================================
// Flash attention (R14 restored): 1 slab/CTA, 1024 CTAs, LPT, fp16 1-term,
// fp32 ex2 softmax both passes, 5 CTAs/SM.
// ===========================================================================
#define AT_K_H(buf) ((buf) * 5120u)
#define AT_V_H(buf) (10240u + (buf) * 9216u)
#define AT_Q_H 10240u
#define ATTN_SMEM 28672

__global__ void __launch_bounds__(128, 5)
attn_flash(float* __restrict__ Pout)
{
    extern __shared__ unsigned char sm[];
    const uint32_t smb = smem_u32(sm);

    const int bh = blockIdx.x;
    const int qs = 15 - (int)blockIdx.y;
    const int q0 = qs * 64;
    const int nkt = qs + 1;
    const int ncol = nkt * 64;
    const int tid = threadIdx.x, wid = tid >> 5, lane = tid & 31;

    const int frow = tid >> 1;
    const int fs2  = (tid & 1) * 2;
    const int fs4  = (tid & 1) * 4;

#define KFILL(buf, kt)                                                            \
    {                                                                             \
        const __half* sh_ = g_K1h + ((size_t)bh*1024 + (size_t)(kt)*64 + frow)*32 + fs2*8; \
        uint32_t d_ = (uint32_t)(frow * 80 + fs2 * 16);                           \
        cp16(smb + AT_K_H(buf) + d_,      sh_);                                   \
        cp16(smb + AT_K_H(buf) + d_ + 16, sh_ + 8);                               \
    }
#define VFILL(buf, kt)                                                            \
    {                                                                             \
        const __half* sh_ = g_Vh + ((size_t)bh*1024 + (size_t)(kt)*64 + frow)*64 + fs4*8; \
        uint32_t d_ = (uint32_t)(frow * 144 + fs4 * 16);                          \
        _Pragma("unroll")                                                         \
        for (int u_ = 0; u_ < 4; ++u_)                                            \
            cp16(smb + AT_V_H(buf) + d_ + u_*16, sh_ + u_*8);                     \
    }

    KFILL(0, 0); CP_COMMIT();

    {
        const __half* qh = g_Q1h + ((size_t)bh*1024 + q0 + frow)*32 + fs2*8;
        uint32_t d = (uint32_t)(frow * 80 + fs2 * 16);
        *(uint4*)(sm + AT_Q_H + d)      = *(const uint4*)qh;
        *(uint4*)(sm + AT_Q_H + d + 16) = *(const uint4*)(qh + 8);
    }
    __syncthreads();

    uint32_t qfh[2][4];
    #pragma unroll
    for (int ks = 0; ks < 2; ++ks) {
        uint32_t off = (uint32_t)((wid * 16 + (lane & 15)) * 80
                                  + ks * 32 + ((lane >> 4) & 1) * 16);
        ldsm_x4(qfh[ks][0], qfh[ks][1], qfh[ks][2], qfh[ks][3], smb + AT_Q_H + off);
    }

    const int gr0 = q0 + wid * 16 + (lane >> 2);
    const uint32_t kfoff = (uint32_t)(((lane & 7)) * 80 + (lane >> 3) * 16);

    #define SCOMP(buf)                                                            \
    {                                                                             \
        const uint32_t khb = smb + AT_K_H(buf) + kfoff;                           \
        _Pragma("unroll")                                                         \
        for (int nt = 0; nt < 8; ++nt) {                                          \
            uint32_t kb[4];                                                       \
            ldsm_x4(kb[0], kb[1], kb[2], kb[3], khb + (uint32_t)(nt * 8 * 80));   \
            mma_f16(s[nt], qfh[0][0], qfh[0][1], qfh[0][2], qfh[0][3], kb[0], kb[1]); \
            mma_f16(s[nt], qfh[1][0], qfh[1][1], qfh[1][2], qfh[1][3], kb[2], kb[3]); \
        }                                                                         \
    }
    #define SMASK(kt)                                                             \
    if ((kt) == nkt - 1) {                                                        \
        int cb = (kt) * 64 + (lane & 3) * 2;                                      \
        _Pragma("unroll")                                                         \
        for (int nt = 0; nt < 8; ++nt) {                                          \
            int c0 = cb + nt * 8;                                                 \
            if (c0     > gr0)     s[nt][0] = -1e30f;                              \
            if (c0 + 1 > gr0)     s[nt][1] = -1e30f;                              \
            if (c0     > gr0 + 8) s[nt][2] = -1e30f;                              \
            if (c0 + 1 > gr0 + 8) s[nt][3] = -1e30f;                              \
        }                                                                         \
    }

    // ================= Pass 1: l = sum exp2(s), fp32 ex2 =================
    float l0 = 0.f, l1 = 0.f;

    for (int kt = 0; kt < nkt; ++kt) {
        CP_WAIT(0);
        __syncthreads();
        if (kt + 1 < nkt) { KFILL((kt + 1) & 1, kt + 1); CP_COMMIT(); }

        float s[8][4] = {};
        SCOMP(kt & 1);
        SMASK(kt);

        float a0 = 0.f, a1 = 0.f;
        #pragma unroll
        for (int nt = 0; nt < 8; ++nt) {
            a0 += ex2f(s[nt][0]) + ex2f(s[nt][1]);
            a1 += ex2f(s[nt][2]) + ex2f(s[nt][3]);
        }
        a0 += __shfl_xor_sync(0xffffffffu, a0, 1);
        a0 += __shfl_xor_sync(0xffffffffu, a0, 2);
        a1 += __shfl_xor_sync(0xffffffffu, a1, 1);
        a1 += __shfl_xor_sync(0xffffffffu, a1, 2);
        l0 += a0;
        l1 += a1;
    }
    const float li0 = 1.0f / l0, li1 = 1.0f / l1;

    // ================= Pass 2: P write + O = P @ V =================
    __syncthreads();
    KFILL(0, 0); VFILL(0, 0); CP_COMMIT();

    float o[8][4] = {};

    for (int kt = 0; kt < nkt; ++kt) {
        CP_WAIT(0);
        __syncthreads();
        if (kt + 1 < nkt) {
            KFILL((kt + 1) & 1, kt + 1);
            VFILL((kt + 1) & 1, kt + 1);
            CP_COMMIT();
        }

        float s[8][4] = {};
        SCOMP(kt & 1);
        SMASK(kt);

        #pragma unroll
        for (int nt = 0; nt < 8; ++nt) {
            s[nt][0] = ex2f(s[nt][0]) * li0;
            s[nt][1] = ex2f(s[nt][1]) * li0;
            s[nt][2] = ex2f(s[nt][2]) * li1;
            s[nt][3] = ex2f(s[nt][3]) * li1;
        }

        {
            float* pr0 = Pout + ((size_t)bh * 1024 + gr0) * 1024 + kt * 64 + (lane & 3) * 2;
            float* pr1 = pr0 + 8 * 1024;
            #pragma unroll
            for (int nt = 0; nt < 8; ++nt) {
                *(float2*)&pr0[nt * 8] = make_float2(s[nt][0], s[nt][1]);
                *(float2*)&pr1[nt * 8] = make_float2(s[nt][2], s[nt][3]);
            }
        }

        const uint32_t vhb = smb + AT_V_H(kt & 1);
        #pragma unroll
        for (int ksv = 0; ksv < 4; ++ksv) {
            uint32_t ah[4];
            ah[0] = pack_h2(s[2*ksv][0],   s[2*ksv][1]);
            ah[1] = pack_h2(s[2*ksv][2],   s[2*ksv][3]);
            ah[2] = pack_h2(s[2*ksv+1][0], s[2*ksv+1][1]);
            ah[3] = pack_h2(s[2*ksv+1][2], s[2*ksv+1][3]);
            uint32_t vrow = (uint32_t)((ksv * 16 + (lane & 7) + ((lane >> 3) & 1) * 8) * 144
                                       + (lane >> 4) * 16);
            #pragma unroll
            for (int ntv = 0; ntv < 8; ntv += 2) {
                uint32_t v0, v1, v2, v3;
                ldsm_x4t(v0, v1, v2, v3, vhb + vrow + ntv * 16);
                mma_f16(o[ntv],     ah[0], ah[1], ah[2], ah[3], v0, v1);
                mma_f16(o[ntv + 1], ah[0], ah[1], ah[2], ah[3], v2, v3);
            }
        }
    }

    // zero-fill P tail
    {
        float4 z = make_float4(0.f, 0.f, 0.f, 0.f);
        float* base0 = Pout + ((size_t)bh * 1024 + gr0) * 1024;
        float* base1 = base0 + 8 * 1024;
        for (int col = ncol + (lane & 3) * 4; col < 1024; col += 16) {
            *(float4*)&base0[col] = z;
            *(float4*)&base1[col] = z;
        }
    }

    // O epilogue -> qkvh (fp16)
    {
        const int b = bh >> 4, h = bh & 15;
        size_t i0 = ((size_t)(b * 1024 + gr0)) * 1024 + h * 64 + (lane & 3) * 2;
        size_t i1 = i0 + 8 * 1024;
        #pragma unroll
        for (int ntv = 0; ntv < 8; ++ntv) {
            *(uint32_t*)&qkvh[i0 + ntv * 8] = pack_h2(o[ntv][0], o[ntv][1]);
            *(uint32_t*)&qkvh[i1 + ntv * 8] = pack_h2(o[ntv][2], o[ntv][3]);
        }
    }
    #undef KFILL
    #undef VFILL
    #undef SCOMP
    #undef SMASK
}

// ---------------------------------------------------------------------------
// LayerNorm (unchanged)
// ---------------------------------------------------------------------------
__global__ void __launch_bounds__(256)
ln_kernel(const float* __restrict__ gamma,
          const float* __restrict__ beta,
          float* __restrict__ out)
{
    const int row = blockIdx.x;
    const int tid = threadIdx.x;
    const int c4  = tid * 4;
    const int hf  = tid >> 7;
    const int wrp = tid >> 5;

    float4 v = *(const float4*)&g_tmp[(size_t)row * 1024 + c4];
    float s  = v.x + v.y + v.z + v.w;
    float sq = v.x*v.x + v.y*v.y + v.z*v.z + v.w*v.w;
    #pragma unroll
    for (int off = 16; off > 0; off >>= 1) {
        s  += __shfl_xor_sync(0xffffffffu, s,  off);
        sq += __shfl_xor_sync(0xffffffffu, sq, off);
    }
    __shared__ float ss[8], sqq[8];
    if ((tid & 31) == 0) { ss[wrp] = s; sqq[wrp] = sq; }
    __syncthreads();
    float tot = 0.f, totq = 0.f;
    #pragma unroll
    for (int w = 0; w < 4; ++w) { tot += ss[hf * 4 + w]; totq += sqq[hf * 4 + w]; }

    float mu  = tot * (1.0f / 512.0f);
    float var = totq * (1.0f / 512.0f) - mu * mu;
    float rstd = rsqrtf(var + 1e-5f);

    int gc = c4 & 511;
    float4 g = *(const float4*)&gamma[gc];
    float4 b = *(const float4*)&beta[gc];
    float4 r;
    r.x = (v.x - mu) * rstd * g.x + b.x;
    r.y = (v.y - mu) * rstd * g.y + b.y;
    r.z = (v.z - mu) * rstd * g.z + b.z;
    r.w = (v.w - mu) * rstd * g.w + b.w;
    *(float4*)&out[(size_t)row * 1024 + c4] = r;
}

// ---------------------------------------------------------------------------
extern "C" void kernel_launch(void* const* d_in, const int* in_sizes, int n_in,
                              void* d_out, int out_size)
{
    const float* inQ  = (const float*)d_in[0];
    const float* inK  = (const float*)d_in[1];
    const float* inV  = (const float*)d_in[2];
    const float* WQ1  = (const float*)d_in[4];
    const float* WK1  = (const float*)d_in[5];
    const float* WV1  = (const float*)d_in[6];
    const float* WV2  = (const float*)d_in[9];
    const float* Wfc1 = (const float*)d_in[10];
    const float* Wfc2 = (const float*)d_in[11];
    const float* ln_g = (const float*)d_in[12];
    const float* ln_b = (const float*)d_in[13];

    float* out  = (float*)d_out;
    float* Pout = out + (size_t)B_ * S_ * D_;

    cudaFuncSetAttribute(attn_flash, cudaFuncAttributeMaxDynamicSharedMemorySize,
                         ATTN_SMEM);
    cudaFuncSetAttribute(mma_gemm, cudaFuncAttributeMaxDynamicSharedMemorySize,
                         GEMM_SMEM);

    // 0) convert GEMM operands to fp16
    presplit<<<dim3(256, 9), 256>>>(inQ, inK, inV, WQ1, WK1, WV1, WV2, Wfc1, Wfc2);
    // 1) projections: Q1, K1, V1, V2 (256x128 tiles, K-chunk 32, 3-stage)
    mma_gemm<<<dim3(16, 4, 4), 512, GEMM_SMEM>>>(inQ, 0);
    // 2) flash attention
    attn_flash<<<dim3(64, 16), 128, ATTN_SMEM>>>(Pout);
    // 3) FC + residual (single wave)
    mma_gemm<<<dim3(16, 4, 2), 512, GEMM_SMEM>>>(inQ, 4);
    // 4) LayerNorm -> final output
    ln_kernel<<<dim3(B_ * S_), 256>>>(ln_g, ln_b, out);
}

// round 17
// speedup vs baseline: 1.0733x; 1.0040x over previous
#include <cuda_runtime.h>
#include <cuda_fp16.h>
#include <math.h>
#include <stdint.h>

// Problem constants
#define B_  4
#define S_  1024
#define D_  1024
#define H_  16
#define DKH_ 32
#define DV_  64

// ---------------------------------------------------------------------------
// Scratch (device globals; no allocations allowed) — all fp16 hi-only
// ---------------------------------------------------------------------------
__device__ __half pQh[4096*512];
__device__ __half pKh[4096*512];
__device__ __half pVh_[4096*1024];
__device__ __half pWh[6*512*512];
__device__ __half g_Q1h[64*1024*32];   // pre-scaled by log2e/sqrt(32)
__device__ __half g_K1h[64*1024*32];
__device__ __half g_Vh [64*1024*64];
__device__ __half qkvh[4096*1024];
__device__ float g_tmp[B_*S_*D_];

// ===========================================================================
// helpers
// ===========================================================================
__device__ __forceinline__ uint32_t smem_u32(const void* p) {
    uint32_t a;
    asm("{ .reg .u64 t; cvta.to.shared.u64 t, %1; cvt.u32.u64 %0, t; }"
        : "=r"(a) : "l"(p));
    return a;
}
__device__ __forceinline__ void ldsm_x4(uint32_t& r0, uint32_t& r1,
                                        uint32_t& r2, uint32_t& r3, uint32_t addr) {
    asm volatile("ldmatrix.sync.aligned.m8n8.x4.shared.b16 {%0,%1,%2,%3}, [%4];"
                 : "=r"(r0), "=r"(r1), "=r"(r2), "=r"(r3) : "r"(addr));
}
__device__ __forceinline__ void ldsm_x4t(uint32_t& r0, uint32_t& r1,
                                         uint32_t& r2, uint32_t& r3, uint32_t addr) {
    asm volatile("ldmatrix.sync.aligned.m8n8.x4.trans.shared.b16 {%0,%1,%2,%3}, [%4];"
                 : "=r"(r0), "=r"(r1), "=r"(r2), "=r"(r3) : "r"(addr));
}
__device__ __forceinline__ void mma_f16(float* c, uint32_t a0, uint32_t a1,
                                        uint32_t a2, uint32_t a3,
                                        uint32_t b0, uint32_t b1) {
    asm volatile("mma.sync.aligned.m16n8k16.row.col.f32.f16.f16.f32 "
                 "{%0,%1,%2,%3}, {%4,%5,%6,%7}, {%8,%9}, {%0,%1,%2,%3};"
                 : "+f"(c[0]), "+f"(c[1]), "+f"(c[2]), "+f"(c[3])
                 : "r"(a0), "r"(a1), "r"(a2), "r"(a3), "r"(b0), "r"(b1));
}
__device__ __forceinline__ float ex2f(float x) {
    float r;
    asm("ex2.approx.f32 %0, %1;" : "=f"(r) : "f"(x));
    return r;
}
__device__ __forceinline__ uint32_t pack_h2(float x, float y) {
    __half2 t = __floats2half2_rn(x, y);
    return *reinterpret_cast<uint32_t*>(&t);
}
__device__ __forceinline__ void cp16(uint32_t dst, const void* src) {
    asm volatile("cp.async.cg.shared.global [%0], [%1], 16;"
                 :: "r"(dst), "l"(src));
}
#define CP_COMMIT()  asm volatile("cp.async.commit_group;" ::: "memory")
#define CP_WAIT(N)   asm volatile("cp.async.wait_group %0;" :: "n"(N) : "memory")

// ===========================================================================
// presplit: fp32 -> fp16 hi for all GEMM operands. (unchanged)
// ===========================================================================
__global__ void __launch_bounds__(256)
presplit(const float* __restrict__ inQ, const float* __restrict__ inK,
         const float* __restrict__ inV,
         const float* __restrict__ W0, const float* __restrict__ W1,
         const float* __restrict__ W2, const float* __restrict__ W3,
         const float* __restrict__ W4, const float* __restrict__ W5)
{
    const int seg = blockIdx.y;
    const int gid = blockIdx.x * 256 + threadIdx.x;
    const int stride4 = gridDim.x * 256 * 4;

    if (seg < 2) {
        const float* s = seg ? inK : inQ;
        __half* dh = seg ? pKh : pQh;
        for (int i = gid * 4; i < 4096 * 512; i += stride4) {
            int row = i >> 9, col = i & 511;
            float4 v = *(const float4*)&s[(size_t)row * 1024 + col];
            *(uint2*)&dh[i] = make_uint2(pack_h2(v.x, v.y), pack_h2(v.z, v.w));
        }
    } else if (seg == 2) {
        for (int i = gid * 4; i < 4096 * 1024; i += stride4) {
            float4 v = *(const float4*)&inV[i];
            *(uint2*)&pVh_[i] = make_uint2(pack_h2(v.x, v.y), pack_h2(v.z, v.w));
        }
    } else {
        const int w = seg - 3;
        const float* s = (w == 0) ? W0 : (w == 1) ? W1 : (w == 2) ? W2
                       : (w == 3) ? W3 : (w == 4) ? W4 : W5;
        __half* dh = pWh + (size_t)w * 262144;
        for (int i = gid * 4; i < 262144; i += stride4) {
            float4 v = *(const float4*)&s[i];
            *(uint2*)&dh[i] = make_uint2(pack_h2(v.x, v.y), pack_h2(v.z, v.w));
        }
    }
}

// ===========================================================================
// HMMA GEMM: 256 threads / 8 warps, CTA tile 128x128, warp tile 64x32,
// K chunk 32, 3-stage cp.async pipeline, 2 CTAs/SM (independent barriers).
// mode: 0=Q1(scaled), 1=K1, 2=V1, 3=V2, 4=FC half0 (+res), 5=FC half1 (+res)
// ===========================================================================
#define APITCH 80
#define BPITCH 272
#define ST_SZ  18944u
#define ST_AH(s) ((s) * ST_SZ)
#define ST_BH(s) ((s) * ST_SZ + 10240u)
#define GEMM_SMEM (3 * 18944)

__global__ void __launch_bounds__(256, 2)
mma_gemm(const float* __restrict__ inQ, int mode_base)
{
    extern __shared__ unsigned char sm[];
    const uint32_t smb = smem_u32(sm);

    const int mode = mode_base + blockIdx.z;
    const __half *pAh;
    int apitch, aoff;
    switch (mode) {
        case 0: pAh = pQh;  apitch = 512;  aoff = 0;   break;
        case 1: pAh = pKh;  apitch = 512;  aoff = 0;   break;
        case 2: pAh = pVh_; apitch = 1024; aoff = 0;   break;
        case 3: pAh = pVh_; apitch = 1024; aoff = 512; break;
        case 4: pAh = qkvh; apitch = 1024; aoff = 0;   break;
        default:pAh = qkvh; apitch = 1024; aoff = 512; break;
    }
    const __half* wh = pWh + (size_t)mode * 262144;

    const int m0 = blockIdx.x * 128;
    const int n0 = blockIdx.y * 128;
    const int tid  = threadIdx.x;
    const int wid  = tid >> 5;
    const int lane = tid & 31;
    const int wy = wid >> 2;        // 0..1 (64 rows each)
    const int wx = wid & 3;         // 0..3 (32 cols each)

    // fills per chunk: A 128x32 = 512 cp16 (2/thread); B 32x128 = 512 (2/thread)
    const int ar = tid >> 1, aseg2 = (tid & 1) * 2;
    const int br = tid >> 3, b2 = (tid & 7) * 2;

    #define GFILL(st, k0)                                                         \
    {                                                                             \
        const __half* sha = pAh + (size_t)(m0 + ar) * apitch + aoff + (k0) + aseg2 * 8; \
        uint32_t da = (uint32_t)(ar * APITCH + aseg2 * 16);                       \
        cp16(smb + ST_AH(st) + da,      sha);                                     \
        cp16(smb + ST_AH(st) + da + 16, sha + 8);                                 \
        const __half* shb = wh + (size_t)((k0) + br) * 512 + n0 + b2 * 8;         \
        uint32_t db = (uint32_t)(br * BPITCH + b2 * 16);                          \
        cp16(smb + ST_BH(st) + db,      shb);                                     \
        cp16(smb + ST_BH(st) + db + 16, shb + 8);                                 \
        CP_COMMIT();                                                              \
    }

    float c[4][4][4] = {};

    const int a_row_in_tile = lane & 15;
    const int a_kseg        = (lane >> 4) & 1;
    const int b_krow        = (lane & 7) + ((lane >> 3) & 1) * 8;
    const int b_colsel      = (lane >> 4) * 16;

    GFILL(0, 0);
    GFILL(1, 32);

    for (int chunk = 0; chunk < 16; ++chunk) {
        if (chunk + 1 < 16) { CP_WAIT(1); } else { CP_WAIT(0); }
        __syncthreads();
        if (chunk + 2 < 16) {
            int st = (chunk + 2) % 3;
            GFILL(st, (chunk + 2) * 32);
        }
        const int cs = chunk % 3;
        const uint32_t ahb = smb + ST_AH(cs);
        const uint32_t bhb = smb + ST_BH(cs);

        #pragma unroll
        for (int ks = 0; ks < 2; ++ks) {
            uint32_t ahf[4][4];
            #pragma unroll
            for (int mt = 0; mt < 4; ++mt) {
                int row = wy * 64 + mt * 16 + a_row_in_tile;
                uint32_t aoffb = (uint32_t)(row * APITCH + ks * 32 + a_kseg * 16);
                ldsm_x4(ahf[mt][0], ahf[mt][1], ahf[mt][2], ahf[mt][3], ahb + aoffb);
            }
            uint32_t bhf[4][2];
            #pragma unroll
            for (int nt2 = 0; nt2 < 4; nt2 += 2) {
                uint32_t boffb = (uint32_t)((ks * 16 + b_krow) * BPITCH
                                            + (wx * 32 + nt2 * 8) * 2 + b_colsel);
                ldsm_x4t(bhf[nt2][0], bhf[nt2][1], bhf[nt2+1][0], bhf[nt2+1][1],
                         bhb + boffb);
            }
            #pragma unroll
            for (int mt = 0; mt < 4; ++mt) {
                #pragma unroll
                for (int nt = 0; nt < 4; ++nt) {
                    mma_f16(c[mt][nt], ahf[mt][0], ahf[mt][1], ahf[mt][2], ahf[mt][3],
                            bhf[nt][0], bhf[nt][1]);
                }
            }
        }
    }

    // ---- epilogue ----
    const int gid = lane >> 2;
    const int tig = lane & 3;

    #pragma unroll
    for (int mt = 0; mt < 4; ++mt) {
        int row = m0 + wy * 64 + mt * 16 + gid;
        int b = row >> 10, s = row & 1023;
        #pragma unroll
        for (int nt = 0; nt < 4; ++nt) {
            int col = n0 + wx * 32 + nt * 8 + tig * 2;
            float2 v01 = make_float2(c[mt][nt][0], c[mt][nt][1]);
            float2 v23 = make_float2(c[mt][nt][2], c[mt][nt][3]);
            if (mode <= 1) {
                int h = col >> 5, d = col & 31;
                __half* dh = (mode == 0) ? g_Q1h : g_K1h;
                // Q scale: log2(e)/sqrt(32) so softmax uses ex2 directly
                float sc = (mode == 0) ? 0.25503487350122697f : 1.0f;
                size_t base = ((size_t)(b * 16 + h) * 1024) * 32 + d;
                *(uint32_t*)&dh[base + (size_t)s * 32]       = pack_h2(v01.x * sc, v01.y * sc);
                *(uint32_t*)&dh[base + (size_t)(s + 8) * 32] = pack_h2(v23.x * sc, v23.y * sc);
            } else if (mode <= 3) {
                int h = col >> 5, d = (col & 31) + (mode == 3 ? 32 : 0);
                size_t base = ((size_t)(b * 16 + h) * 1024) * 64 + d;
                *(uint32_t*)&g_Vh[base + (size_t)s * 64]       = pack_h2(v01.x, v01.y);
                *(uint32_t*)&g_Vh[base + (size_t)(s + 8) * 64] = pack_h2(v23.x, v23.y);
            } else {
                int half = mode - 4;
                size_t idx0 = (size_t)row * 1024 + half * 512 + col;
                size_t idx1 = idx0 + 8 * 1024;
                float2 r0 = *(const float2*)&inQ[idx0];
                float2 r1 = *(const float2*)&inQ[idx1];
                *(float2*)&g_tmp[idx0] = make_float2(v01.x + r0.x, v01.y + r0.y);
                *(float2*)&g_tmp[idx1] = make_float2(v23.x + r1.x, v23.y + r1.y);
            }
        }
    }
    #undef GFILL
}

// ===========================================================================
// Flash attention (unchanged, proven): 1 slab/CTA, 1024 CTAs, LPT,
// fp16 1-term, fp32 ex2 softmax, 5 CTAs/SM.
// ===========================================================================
#define AT_K_H(buf) ((buf) * 5120u)
#define AT_V_H(buf) (10240u + (buf) * 9216u)
#define AT_Q_H 10240u
#define ATTN_SMEM 28672

__global__ void __launch_bounds__(128, 5)
attn_flash(float* __restrict__ Pout)
{
    extern __shared__ unsigned char sm[];
    const uint32_t smb = smem_u32(sm);

    const int bh = blockIdx.x;
    const int qs = 15 - (int)blockIdx.y;
    const int q0 = qs * 64;
    const int nkt = qs + 1;
    const int ncol = nkt * 64;
    const int tid = threadIdx.x, wid = tid >> 5, lane = tid & 31;

    const int frow = tid >> 1;
    const int fs2  = (tid & 1) * 2;
    const int fs4  = (tid & 1) * 4;

#define KFILL(buf, kt)                                                            \
    {                                                                             \
        const __half* sh_ = g_K1h + ((size_t)bh*1024 + (size_t)(kt)*64 + frow)*32 + fs2*8; \
        uint32_t d_ = (uint32_t)(frow * 80 + fs2 * 16);                           \
        cp16(smb + AT_K_H(buf) + d_,      sh_);                                   \
        cp16(smb + AT_K_H(buf) + d_ + 16, sh_ + 8);                               \
    }
#define VFILL(buf, kt)                                                            \
    {                                                                             \
        const __half* sh_ = g_Vh + ((size_t)bh*1024 + (size_t)(kt)*64 + frow)*64 + fs4*8; \
        uint32_t d_ = (uint32_t)(frow * 144 + fs4 * 16);                          \
        _Pragma("unroll")                                                         \
        for (int u_ = 0; u_ < 4; ++u_)                                            \
            cp16(smb + AT_V_H(buf) + d_ + u_*16, sh_ + u_*8);                     \
    }

    KFILL(0, 0); CP_COMMIT();

    {
        const __half* qh = g_Q1h + ((size_t)bh*1024 + q0 + frow)*32 + fs2*8;
        uint32_t d = (uint32_t)(frow * 80 + fs2 * 16);
        *(uint4*)(sm + AT_Q_H + d)      = *(const uint4*)qh;
        *(uint4*)(sm + AT_Q_H + d + 16) = *(const uint4*)(qh + 8);
    }
    __syncthreads();

    uint32_t qfh[2][4];
    #pragma unroll
    for (int ks = 0; ks < 2; ++ks) {
        uint32_t off = (uint32_t)((wid * 16 + (lane & 15)) * 80
                                  + ks * 32 + ((lane >> 4) & 1) * 16);
        ldsm_x4(qfh[ks][0], qfh[ks][1], qfh[ks][2], qfh[ks][3], smb + AT_Q_H + off);
    }

    const int gr0 = q0 + wid * 16 + (lane >> 2);
    const uint32_t kfoff = (uint32_t)(((lane & 7)) * 80 + (lane >> 3) * 16);

    #define SCOMP(buf)                                                            \
    {                                                                             \
        const uint32_t khb = smb + AT_K_H(buf) + kfoff;                           \
        _Pragma("unroll")                                                         \
        for (int nt = 0; nt < 8; ++nt) {                                          \
            uint32_t kb[4];                                                       \
            ldsm_x4(kb[0], kb[1], kb[2], kb[3], khb + (uint32_t)(nt * 8 * 80));   \
            mma_f16(s[nt], qfh[0][0], qfh[0][1], qfh[0][2], qfh[0][3], kb[0], kb[1]); \
            mma_f16(s[nt], qfh[1][0], qfh[1][1], qfh[1][2], qfh[1][3], kb[2], kb[3]); \
        }                                                                         \
    }
    #define SMASK(kt)                                                             \
    if ((kt) == nkt - 1) {                                                        \
        int cb = (kt) * 64 + (lane & 3) * 2;                                      \
        _Pragma("unroll")                                                         \
        for (int nt = 0; nt < 8; ++nt) {                                          \
            int c0 = cb + nt * 8;                                                 \
            if (c0     > gr0)     s[nt][0] = -1e30f;                              \
            if (c0 + 1 > gr0)     s[nt][1] = -1e30f;                              \
            if (c0     > gr0 + 8) s[nt][2] = -1e30f;                              \
            if (c0 + 1 > gr0 + 8) s[nt][3] = -1e30f;                              \
        }                                                                         \
    }

    // ================= Pass 1: l = sum exp2(s), fp32 ex2 =================
    float l0 = 0.f, l1 = 0.f;

    for (int kt = 0; kt < nkt; ++kt) {
        CP_WAIT(0);
        __syncthreads();
        if (kt + 1 < nkt) { KFILL((kt + 1) & 1, kt + 1); CP_COMMIT(); }

        float s[8][4] = {};
        SCOMP(kt & 1);
        SMASK(kt);

        float a0 = 0.f, a1 = 0.f;
        #pragma unroll
        for (int nt = 0; nt < 8; ++nt) {
            a0 += ex2f(s[nt][0]) + ex2f(s[nt][1]);
            a1 += ex2f(s[nt][2]) + ex2f(s[nt][3]);
        }
        a0 += __shfl_xor_sync(0xffffffffu, a0, 1);
        a0 += __shfl_xor_sync(0xffffffffu, a0, 2);
        a1 += __shfl_xor_sync(0xffffffffu, a1, 1);
        a1 += __shfl_xor_sync(0xffffffffu, a1, 2);
        l0 += a0;
        l1 += a1;
    }
    const float li0 = 1.0f / l0, li1 = 1.0f / l1;

    // ================= Pass 2: P write + O = P @ V =================
    __syncthreads();
    KFILL(0, 0); VFILL(0, 0); CP_COMMIT();

    float o[8][4] = {};

    for (int kt = 0; kt < nkt; ++kt) {
        CP_WAIT(0);
        __syncthreads();
        if (kt + 1 < nkt) {
            KFILL((kt + 1) & 1, kt + 1);
            VFILL((kt + 1) & 1, kt + 1);
            CP_COMMIT();
        }

        float s[8][4] = {};
        SCOMP(kt & 1);
        SMASK(kt);

        #pragma unroll
        for (int nt = 0; nt < 8; ++nt) {
            s[nt][0] = ex2f(s[nt][0]) * li0;
            s[nt][1] = ex2f(s[nt][1]) * li0;
            s[nt][2] = ex2f(s[nt][2]) * li1;
            s[nt][3] = ex2f(s[nt][3]) * li1;
        }

        {
            float* pr0 = Pout + ((size_t)bh * 1024 + gr0) * 1024 + kt * 64 + (lane & 3) * 2;
            float* pr1 = pr0 + 8 * 1024;
            #pragma unroll
            for (int nt = 0; nt < 8; ++nt) {
                *(float2*)&pr0[nt * 8] = make_float2(s[nt][0], s[nt][1]);
                *(float2*)&pr1[nt * 8] = make_float2(s[nt][2], s[nt][3]);
            }
        }

        const uint32_t vhb = smb + AT_V_H(kt & 1);
        #pragma unroll
        for (int ksv = 0; ksv < 4; ++ksv) {
            uint32_t ah[4];
            ah[0] = pack_h2(s[2*ksv][0],   s[2*ksv][1]);
            ah[1] = pack_h2(s[2*ksv][2],   s[2*ksv][3]);
            ah[2] = pack_h2(s[2*ksv+1][0], s[2*ksv+1][1]);
            ah[3] = pack_h2(s[2*ksv+1][2], s[2*ksv+1][3]);
            uint32_t vrow = (uint32_t)((ksv * 16 + (lane & 7) + ((lane >> 3) & 1) * 8) * 144
                                       + (lane >> 4) * 16);
            #pragma unroll
            for (int ntv = 0; ntv < 8; ntv += 2) {
                uint32_t v0, v1, v2, v3;
                ldsm_x4t(v0, v1, v2, v3, vhb + vrow + ntv * 16);
                mma_f16(o[ntv],     ah[0], ah[1], ah[2], ah[3], v0, v1);
                mma_f16(o[ntv + 1], ah[0], ah[1], ah[2], ah[3], v2, v3);
            }
        }
    }

    // zero-fill P tail
    {
        float4 z = make_float4(0.f, 0.f, 0.f, 0.f);
        float* base0 = Pout + ((size_t)bh * 1024 + gr0) * 1024;
        float* base1 = base0 + 8 * 1024;
        for (int col = ncol + (lane & 3) * 4; col < 1024; col += 16) {
            *(float4*)&base0[col] = z;
            *(float4*)&base1[col] = z;
        }
    }

    // O epilogue -> qkvh (fp16)
    {
        const int b = bh >> 4, h = bh & 15;
        size_t i0 = ((size_t)(b * 1024 + gr0)) * 1024 + h * 64 + (lane & 3) * 2;
        size_t i1 = i0 + 8 * 1024;
        #pragma unroll
        for (int ntv = 0; ntv < 8; ++ntv) {
            *(uint32_t*)&qkvh[i0 + ntv * 8] = pack_h2(o[ntv][0], o[ntv][1]);
            *(uint32_t*)&qkvh[i1 + ntv * 8] = pack_h2(o[ntv][2], o[ntv][3]);
        }
    }
    #undef KFILL
    #undef VFILL
    #undef SCOMP
    #undef SMASK
}

// ---------------------------------------------------------------------------
// LayerNorm (unchanged)
// ---------------------------------------------------------------------------
__global__ void __launch_bounds__(256)
ln_kernel(const float* __restrict__ gamma,
          const float* __restrict__ beta,
          float* __restrict__ out)
{
    const int row = blockIdx.x;
    const int tid = threadIdx.x;
    const int c4  = tid * 4;
    const int hf  = tid >> 7;
    const int wrp = tid >> 5;

    float4 v = *(const float4*)&g_tmp[(size_t)row * 1024 + c4];
    float s  = v.x + v.y + v.z + v.w;
    float sq = v.x*v.x + v.y*v.y + v.z*v.z + v.w*v.w;
    #pragma unroll
    for (int off = 16; off > 0; off >>= 1) {
        s  += __shfl_xor_sync(0xffffffffu, s,  off);
        sq += __shfl_xor_sync(0xffffffffu, sq, off);
    }
    __shared__ float ss[8], sqq[8];
    if ((tid & 31) == 0) { ss[wrp] = s; sqq[wrp] = sq; }
    __syncthreads();
    float tot = 0.f, totq = 0.f;
    #pragma unroll
    for (int w = 0; w < 4; ++w) { tot += ss[hf * 4 + w]; totq += sqq[hf * 4 + w]; }

    float mu  = tot * (1.0f / 512.0f);
    float var = totq * (1.0f / 512.0f) - mu * mu;
    float rstd = rsqrtf(var + 1e-5f);

    int gc = c4 & 511;
    float4 g = *(const float4*)&gamma[gc];
    float4 b = *(const float4*)&beta[gc];
    float4 r;
    r.x = (v.x - mu) * rstd * g.x + b.x;
    r.y = (v.y - mu) * rstd * g.y + b.y;
    r.z = (v.z - mu) * rstd * g.z + b.z;
    r.w = (v.w - mu) * rstd * g.w + b.w;
    *(float4*)&out[(size_t)row * 1024 + c4] = r;
}

// ---------------------------------------------------------------------------
extern "C" void kernel_launch(void* const* d_in, const int* in_sizes, int n_in,
                              void* d_out, int out_size)
{
    const float* inQ  = (const float*)d_in[0];
    const float* inK  = (const float*)d_in[1];
    const float* inV  = (const float*)d_in[2];
    const float* WQ1  = (const float*)d_in[4];
    const float* WK1  = (const float*)d_in[5];
    const float* WV1  = (const float*)d_in[6];
    const float* WV2  = (const float*)d_in[9];
    const float* Wfc1 = (const float*)d_in[10];
    const float* Wfc2 = (const float*)d_in[11];
    const float* ln_g = (const float*)d_in[12];
    const float* ln_b = (const float*)d_in[13];

    float* out  = (float*)d_out;
    float* Pout = out + (size_t)B_ * S_ * D_;

    cudaFuncSetAttribute(attn_flash, cudaFuncAttributeMaxDynamicSharedMemorySize,
                         ATTN_SMEM);
    cudaFuncSetAttribute(mma_gemm, cudaFuncAttributeMaxDynamicSharedMemorySize,
                         GEMM_SMEM);

    // 0) convert GEMM operands to fp16
    presplit<<<dim3(256, 9), 256>>>(inQ, inK, inV, WQ1, WK1, WV1, WV2, Wfc1, Wfc2);
    // 1) projections: Q1, K1, V1, V2 (128x128 tiles, 2 CTAs/SM)
    mma_gemm<<<dim3(32, 4, 4), 256, GEMM_SMEM>>>(inQ, 0);
    // 2) flash attention
    attn_flash<<<dim3(64, 16), 128, ATTN_SMEM>>>(Pout);
    // 3) FC + residual (256 CTAs, single wave at 2 CTAs/SM)
    mma_gemm<<<dim3(32, 4, 2), 256, GEMM_SMEM>>>(inQ, 4);
    // 4) LayerNorm -> final output
    ln_kernel<<<dim3(B_ * S_), 256>>>(ln_g, ln_b, out);
}